// round 6
// baseline (speedup 1.0000x reference)
#include <cuda_runtime.h>
#include <math_constants.h>

// x: [4,16,8192] f32 ; weights1: [16,16,64] f32 ; out: [4,16,4097] f32
#define NN    8192
#define MM    64
#define N2    4097
#define NPART 128     // n-chunk blocks
#define NPTOT 512     // total partials (4 groups per block)
#define NBLK  148
#define NTHR  1024

// -------- device scratch --------
__device__ float g_P[NPTOT * 4096];       // partials (8 MB) [pp][r*64+k]
__device__ float g_hq[64 * 256];          // hq transposed: [m][u], u=i*16+o
__device__ float g_u[64 * 64];            // u[r][m]
__device__ float g_v[64 * 64];            // v[r][m]
__device__ float g_zT[64 * 64];           // z transposed: [m'][r]

// -------- grid barrier (1 CTA/SM, all resident) --------
__device__ volatile unsigned g_bar_gen = 0;
__device__ unsigned g_bar_count = 0;

__device__ __forceinline__ void grid_bar()
{
    __syncthreads();
    if (threadIdx.x == 0) {
        __threadfence();
        unsigned gen = g_bar_gen;
        if (atomicAdd(&g_bar_count, 1u) == (unsigned)(NBLK - 1)) {
            g_bar_count = 0;
            __threadfence();
            g_bar_gen = gen + 1u;
        } else {
            while (g_bar_gen == gen) { }
        }
        __threadfence();
    }
    __syncthreads();
}

// -------- shared memory union --------
struct SmemA {
    float Xs[64][68];   // [r][n_local]  row-major, conflict-free
    float Cs[64][68];   // [n_local][k] / [j][m]
    float ws[16][64];
    float v64[64];
};
struct SmemR {
    float red[16][64];
    float Ys[64];
    float hps[64];
    float v64[64];
};
struct SmemZ {
    float u16[16][68];
    float v16[16][68];
    float hzs[16][68];
    float v64[64];
};
struct SmemC {
    float  zs[64][68];  // [m'][r]
    float  Cs[64][36];  // [m'][kt]
    float4 comb[512];   // half-combine scratch
};
union SmemU { SmemA a; SmemR r; SmemZ z; SmemC c; };

__global__ __launch_bounds__(NTHR, 1)
void k_fused(const float* __restrict__ x, const float* __restrict__ w,
             float* __restrict__ out)
{
    __shared__ SmemU sm;
    const int blk = blockIdx.x;
    const int tid = threadIdx.x;

    // ================= PHASE A: GEMM partials + hq =================
    if (blk < NPART) {
        const int n0 = blk * 64;
        // X load, row-major (conflict-free STS.128)
        {
            int row = tid >> 4;
            int c4  = (tid & 15) * 4;
            float4 v = *reinterpret_cast<const float4*>(x + row * NN + n0 + c4);
            *reinterpret_cast<float4*>(&sm.a.Xs[row][c4]) = v;
        }
        // cas table: 4 entries/thread via rotation recurrence
        {
            const float W0 = 2.0f * CUDART_PI_F / 8192.0f;
            const int nl = tid >> 4;
            const int k0 = (tid & 15) * 4;
            unsigned nm = (unsigned)(n0 + nl) & 8191u;
            unsigned t0 = (nm * (unsigned)k0) & 8191u;
            float s0, c0, sd, cd;
            __sincosf((float)t0 * W0, &s0, &c0);
            __sincosf((float)nm * W0, &sd, &cd);
            float c = c0, s = s0;
            #pragma unroll
            for (int j = 0; j < 4; j++) {
                sm.a.Cs[nl][k0 + j] = c + s;
                float cn = fmaf(c, cd, -s * sd);
                float sn = fmaf(s, cd,  c * sd);
                c = cn; s = sn;
            }
        }
        __syncthreads();

        // 4 n-groups of 16, each 256 threads, each writes its own partial
        const int g    = tid >> 8;
        const int tid2 = tid & 255;
        const int kq = tid2 & 15, rq = tid2 >> 4;
        const int r0 = rq * 4, k0 = kq * 4;
        const int nb = g * 16;
        float acc[4][4] = {};
        #pragma unroll
        for (int j = 0; j < 16; j++) {
            int nl = nb + j;
            float x0 = sm.a.Xs[r0 + 0][nl];
            float x1 = sm.a.Xs[r0 + 1][nl];
            float x2 = sm.a.Xs[r0 + 2][nl];
            float x3 = sm.a.Xs[r0 + 3][nl];
            float4 cv = *reinterpret_cast<const float4*>(&sm.a.Cs[nl][k0]);
            acc[0][0] = fmaf(x0, cv.x, acc[0][0]);
            acc[0][1] = fmaf(x0, cv.y, acc[0][1]);
            acc[0][2] = fmaf(x0, cv.z, acc[0][2]);
            acc[0][3] = fmaf(x0, cv.w, acc[0][3]);
            acc[1][0] = fmaf(x1, cv.x, acc[1][0]);
            acc[1][1] = fmaf(x1, cv.y, acc[1][1]);
            acc[1][2] = fmaf(x1, cv.z, acc[1][2]);
            acc[1][3] = fmaf(x1, cv.w, acc[1][3]);
            acc[2][0] = fmaf(x2, cv.x, acc[2][0]);
            acc[2][1] = fmaf(x2, cv.y, acc[2][1]);
            acc[2][2] = fmaf(x2, cv.z, acc[2][2]);
            acc[2][3] = fmaf(x2, cv.w, acc[2][3]);
            acc[3][0] = fmaf(x3, cv.x, acc[3][0]);
            acc[3][1] = fmaf(x3, cv.y, acc[3][1]);
            acc[3][2] = fmaf(x3, cv.z, acc[3][2]);
            acc[3][3] = fmaf(x3, cv.w, acc[3][3]);
        }
        float* P = g_P + (blk * 4 + g) * 4096;
        #pragma unroll
        for (int a = 0; a < 4; a++) {
            float4 v = make_float4(acc[a][0], acc[a][1], acc[a][2], acc[a][3]);
            *reinterpret_cast<float4*>(P + (r0 + a) * 64 + k0) = v;
        }
    } else if (blk < NPART + 16) {
        // hq: rows u0..u0+15, hq[u][m] = sum_j w[u][j]*cas64[j][m] (transposed store)
        const int u0 = (blk - NPART) * 16;
        sm.a.ws[tid >> 6][tid & 63] = w[u0 * 64 + tid];
        if (tid < 64) {
            const float W1 = 2.0f * CUDART_PI_F / 64.0f;
            float s, c;
            __sincosf((float)tid * W1, &s, &c);
            sm.a.v64[tid] = c + s;
        }
        __syncthreads();
        #pragma unroll
        for (int q = 0; q < 4; q++) {
            int idx = tid + q * NTHR;
            int j = idx >> 6, m = idx & 63;
            sm.a.Cs[j][m] = sm.a.v64[(j * m) & 63];
        }
        __syncthreads();
        {
            int ul = tid >> 6, m = tid & 63;
            float acc = 0.f;
            #pragma unroll
            for (int j = 0; j < 64; j++)
                acc = fmaf(sm.a.ws[ul][j], sm.a.Cs[j][m], acc);
            g_hq[m * 256 + u0 + ul] = acc;
        }
    }

    grid_bar();

    // ================= PHASE R: per-row reduce + hp + (u,v) =================
    if (blk < 64) {
        const int r = blk;
        if (tid < 64) {
            const float W1 = 2.0f * CUDART_PI_F / 64.0f;
            float s, c;
            __sincosf((float)tid * W1, &s, &c);
            sm.r.v64[tid] = c + s;
        }
        {
            const int pg = tid >> 6;          // 0..15 groups of 32 partials
            const int k  = tid & 63;
            const float* P = g_P + r * 64 + k + pg * 32 * 4096;
            float a0 = 0.f, a1 = 0.f, a2 = 0.f, a3 = 0.f;
            #pragma unroll
            for (int p = 0; p < 32; p += 4) {
                a0 += P[(p + 0) * 4096];
                a1 += P[(p + 1) * 4096];
                a2 += P[(p + 2) * 4096];
                a3 += P[(p + 3) * 4096];
            }
            sm.r.red[pg][k] = (a0 + a1) + (a2 + a3);
        }
        __syncthreads();
        if (tid < 64) {
            float s = 0.f;
            #pragma unroll
            for (int g = 0; g < 16; g++) s += sm.r.red[g][tid];
            sm.r.Ys[tid] = s;
        }
        __syncthreads();
        if (tid < 64) {
            const int m = tid;
            float acc = 0.f;
            #pragma unroll
            for (int k = 0; k < 64; k++)
                acc = fmaf(sm.r.Ys[k], sm.r.v64[(k * m) & 63], acc);
            sm.r.hps[m] = acc;
        }
        __syncthreads();
        if (tid < 64) {
            const int m = tid, mr = (64 - m) & 63;
            float a = sm.r.hps[m], b2 = sm.r.hps[mr];
            g_u[r * 64 + m] = a + b2;
            g_v[r * 64 + m] = a - b2;
        }
    }

    grid_bar();

    // ===== PHASE Z (blocks 0-3) / C-table pregen (blocks 4-128) =====
    const int kbase = blk * 32;
    if (blk < 4) {
        const int b = blk;
        if (tid < 64) {
            const float W1 = 2.0f * CUDART_PI_F / 64.0f;
            float s, c;
            __sincosf((float)tid * W1, &s, &c);
            sm.z.v64[tid] = c + s;
        }
        {
            int i = tid >> 6, m = tid & 63;
            sm.z.u16[i][m] = g_u[b * 1024 + tid];
            sm.z.v16[i][m] = g_v[b * 1024 + tid];
        }
        __syncthreads();
        {
            int m = tid >> 4, o = tid & 15;
            int mr = (64 - m) & 63;
            const float* hq1 = g_hq + m  * 256 + o;
            const float* hq2 = g_hq + mr * 256 + o;
            float acc = 0.f;
            #pragma unroll
            for (int i = 0; i < 16; i++) {
                acc = fmaf(sm.z.u16[i][m], hq1[i * 16], acc);
                acc = fmaf(sm.z.v16[i][m], hq2[i * 16], acc);
            }
            sm.z.hzs[o][m] = 0.5f * acc;
        }
        __syncthreads();
        {
            int o = tid >> 6, mp = tid & 63;
            float acc = 0.f;
            #pragma unroll
            for (int m = 0; m < 64; m++)
                acc = fmaf(sm.z.hzs[o][m], sm.z.v64[(m * mp) & 63], acc);
            g_zT[mp * 64 + b * 16 + o] = acc * (1.0f / 4096.0f);
        }
    } else if (blk < 129) {
        // pregenerate phase-C cas table (independent of Z)
        const float W2 = 2.0f * CUDART_PI_F / 4097.0f;
        const int mm = tid >> 4;
        const int kt0 = (tid & 15) * 2;
        int k0 = kbase + kt0;
        int t0 = (mm * k0) % 4097;
        float s0, c0, sd, cd;
        __sincosf((float)t0 * W2, &s0, &c0);
        __sincosf((float)mm * W2, &sd, &cd);
        sm.c.Cs[mm][kt0] = c0 + s0;
        float c1 = fmaf(c0, cd, -s0 * sd);
        float s1 = fmaf(s0, cd,  c0 * sd);
        sm.c.Cs[mm][kt0 + 1] = c1 + s1;
    }

    grid_bar();

    // ================= PHASE C: final DHT (129 blocks) =================
    if (blk < 129) {
        if (blk < 4) {
            const float W2 = 2.0f * CUDART_PI_F / 4097.0f;
            const int mm = tid >> 4;
            const int kt0 = (tid & 15) * 2;
            int k0 = kbase + kt0;
            int t0 = (mm * k0) % 4097;
            float s0, c0, sd, cd;
            __sincosf((float)t0 * W2, &s0, &c0);
            __sincosf((float)mm * W2, &sd, &cd);
            sm.c.Cs[mm][kt0] = c0 + s0;
            float c1 = fmaf(c0, cd, -s0 * sd);
            float s1 = fmaf(s0, cd,  c0 * sd);
            sm.c.Cs[mm][kt0 + 1] = c1 + s1;
        }
        // load zT (hot in L2)
        {
            float4 v = *reinterpret_cast<const float4*>(g_zT + tid * 4);
            int f = tid * 4;
            *reinterpret_cast<float4*>(&sm.c.zs[f >> 6][f & 63]) = v;
        }
        __syncthreads();

        // thread: ktq = k-in-chunk, rq5 = (mhalf, row-group of 4)
        const int ktq   = tid & 31;
        const int rq5   = tid >> 5;         // 0..31
        const int mhalf = rq5 >> 4;
        const int rr    = (rq5 & 15) * 4;
        const int k     = kbase + ktq;
        float a0 = 0.f, a1 = 0.f, a2 = 0.f, a3 = 0.f;
        const int mb = mhalf * 32;
        #pragma unroll
        for (int j = 0; j < 32; j++) {
            int mm = mb + j;
            float4 zv = *reinterpret_cast<const float4*>(&sm.c.zs[mm][rr]);
            float cv = sm.c.Cs[mm][ktq];
            a0 = fmaf(zv.x, cv, a0);
            a1 = fmaf(zv.y, cv, a1);
            a2 = fmaf(zv.z, cv, a2);
            a3 = fmaf(zv.w, cv, a3);
        }
        const int ci = (rq5 & 15) * 32 + ktq;
        if (mhalf == 1)
            sm.c.comb[ci] = make_float4(a0, a1, a2, a3);
        __syncthreads();
        if (mhalf == 0 && k < N2) {
            float4 o2 = sm.c.comb[ci];
            const float SCL = 1.0f / 262208.0f;
            out[(rr + 0) * N2 + k] = (a0 + o2.x) * SCL;
            out[(rr + 1) * N2 + k] = (a1 + o2.y) * SCL;
            out[(rr + 2) * N2 + k] = (a2 + o2.z) * SCL;
            out[(rr + 3) * N2 + k] = (a3 + o2.w) * SCL;
        }
    }
}

// ============================================================
extern "C" void kernel_launch(void* const* d_in, const int* in_sizes, int n_in,
                              void* d_out, int out_size)
{
    const float* x = (const float*)d_in[0];   // [4,16,8192]
    const float* w = (const float*)d_in[1];   // [16,16,64]
    float* out = (float*)d_out;               // [4,16,4097]

    k_fused<<<NBLK, NTHR>>>(x, w, out);
}

// round 7
// speedup vs baseline: 1.1756x; 1.1756x over previous
#include <cuda_runtime.h>
#include <math_constants.h>

// x: [4,16,8192] f32 ; weights1: [16,16,64] f32 ; out: [4,16,4097] f32
#define NN    8192
#define N2    4097
#define NGEMM 128     // n-chunk blocks
#define NPTOT 256     // partials (2 halves per block)
#define NBLK  148
#define NTHR  512

// -------- device scratch --------
__device__ float g_P[NPTOT * 4096];       // partials (4 MB) [p][r*64+k]
__device__ float g_hq[64 * 256];          // hq transposed: [m][u], u=i*16+o
__device__ float g_u[64 * 64];            // u[r][m]
__device__ float g_v[64 * 64];            // v[r][m]
__device__ float g_zT[64 * 64];           // z transposed: [m'][r]

// -------- grid barrier (1 CTA/SM, all resident) --------
__device__ volatile unsigned g_bar_gen = 0;
__device__ unsigned g_bar_count = 0;

__device__ __forceinline__ void grid_bar()
{
    __syncthreads();
    if (threadIdx.x == 0) {
        __threadfence();
        unsigned gen = g_bar_gen;
        if (atomicAdd(&g_bar_count, 1u) == (unsigned)(NBLK - 1)) {
            g_bar_count = 0;
            __threadfence();
            g_bar_gen = gen + 1u;
        } else {
            while (g_bar_gen == gen) __nanosleep(32);
        }
        __threadfence();
    }
    __syncthreads();
}

// -------- shared memory --------
struct SmemA {
    float Xs[64][68];   // [r][n_local] row-major
    float Cs[64][68];   // [n_local][k] / [j][m]
    float ws[16][64];
    float v64[64];
};
struct SmemR {
    float red[8][64];
    float Ys[64];
    float hps[64];
    float v64[64];
};
struct SmemZ {
    float u16[16][68];
    float v16[16][68];
    float hzs[16][68];
    float v64[64];
};
struct SmemC {
    float zs[64][68];   // [m'][r]
    float Cs[64][36];   // [m'][kt]
};
union SmemU { SmemA a; SmemR r; SmemZ z; SmemC c; };

// phase-C cas table: column recurrence, 64 threads, 256 MUFU total
__device__ __forceinline__ void gen_ctab(float (*Cs)[36], int kbase, int tid)
{
    if (tid < 64) {
        const float W2 = 2.0f * CUDART_PI_F / 4097.0f;
        int kt = tid & 31, h = tid >> 5;
        int k = kbase + kt;
        int t0 = (k * (h * 32)) % 4097;
        int d  = k % 4097;
        float s, c, sd, cd;
        __sincosf((float)t0 * W2, &s, &c);
        __sincosf((float)d  * W2, &sd, &cd);
        #pragma unroll
        for (int j = 0; j < 32; j++) {
            Cs[h * 32 + j][kt] = c + s;
            float cn = fmaf(c, cd, -s * sd);
            float sn = fmaf(s, cd,  c * sd);
            c = cn; s = sn;
        }
    }
}

__global__ __launch_bounds__(NTHR, 1)
void k_fused(const float* __restrict__ x, const float* __restrict__ w,
             float* __restrict__ out)
{
    __shared__ SmemU sm;
    const int blk = blockIdx.x;
    const int tid = threadIdx.x;
    const int kbase = blk * 32;

    // ================= PHASE A: GEMM partials + hq =================
    if (blk < NGEMM) {
        const int n0 = blk * 64;
        // issue X loads into registers FIRST (hide DRAM under MUFU)
        const int row = tid >> 3;
        const int c8  = (tid & 7) * 8;
        float4 xa = *reinterpret_cast<const float4*>(x + row * NN + n0 + c8);
        float4 xb = *reinterpret_cast<const float4*>(x + row * NN + n0 + c8 + 4);

        // cas table via COLUMN recurrence: 128 threads, 2 sincos each
        if (tid < 128) {
            const float W0 = 2.0f * CUDART_PI_F / 8192.0f;
            int k = tid & 63, h = tid >> 6;
            unsigned t0 = ((unsigned)(n0 + 32 * h) * (unsigned)k) & 8191u;
            float s, c, sd, cd;
            __sincosf((float)t0 * W0, &s, &c);
            __sincosf((float)k  * W0, &sd, &cd);
            #pragma unroll
            for (int j = 0; j < 32; j++) {
                sm.a.Cs[h * 32 + j][k] = c + s;
                float cn = fmaf(c, cd, -s * sd);
                float sn = fmaf(s, cd,  c * sd);
                c = cn; s = sn;
            }
        }
        // store X regs to smem (row-major, conflict-free)
        *reinterpret_cast<float4*>(&sm.a.Xs[row][c8])     = xa;
        *reinterpret_cast<float4*>(&sm.a.Xs[row][c8 + 4]) = xb;
        __syncthreads();

        // GEMM: halves over n, each writes its own partial
        const int half = tid >> 8;
        const int tid2 = tid & 255;
        const int kq = tid2 & 15, rq = tid2 >> 4;
        const int r0 = rq * 4, k0 = kq * 4;
        const int nb = half * 32;
        float acc[4][4] = {};
        #pragma unroll
        for (int j = 0; j < 32; j++) {
            int nl = nb + j;
            float x0 = sm.a.Xs[r0 + 0][nl];
            float x1 = sm.a.Xs[r0 + 1][nl];
            float x2 = sm.a.Xs[r0 + 2][nl];
            float x3 = sm.a.Xs[r0 + 3][nl];
            float4 cv = *reinterpret_cast<const float4*>(&sm.a.Cs[nl][k0]);
            acc[0][0] = fmaf(x0, cv.x, acc[0][0]);
            acc[0][1] = fmaf(x0, cv.y, acc[0][1]);
            acc[0][2] = fmaf(x0, cv.z, acc[0][2]);
            acc[0][3] = fmaf(x0, cv.w, acc[0][3]);
            acc[1][0] = fmaf(x1, cv.x, acc[1][0]);
            acc[1][1] = fmaf(x1, cv.y, acc[1][1]);
            acc[1][2] = fmaf(x1, cv.z, acc[1][2]);
            acc[1][3] = fmaf(x1, cv.w, acc[1][3]);
            acc[2][0] = fmaf(x2, cv.x, acc[2][0]);
            acc[2][1] = fmaf(x2, cv.y, acc[2][1]);
            acc[2][2] = fmaf(x2, cv.z, acc[2][2]);
            acc[2][3] = fmaf(x2, cv.w, acc[2][3]);
            acc[3][0] = fmaf(x3, cv.x, acc[3][0]);
            acc[3][1] = fmaf(x3, cv.y, acc[3][1]);
            acc[3][2] = fmaf(x3, cv.z, acc[3][2]);
            acc[3][3] = fmaf(x3, cv.w, acc[3][3]);
        }
        float* P = g_P + (blk * 2 + half) * 4096;
        #pragma unroll
        for (int a = 0; a < 4; a++)
            *reinterpret_cast<float4*>(P + (r0 + a) * 64 + k0) =
                make_float4(acc[a][0], acc[a][1], acc[a][2], acc[a][3]);
    } else if (blk < NGEMM + 16) {
        // hq: rows u0..u0+15, hq[u][m] = sum_j w[u][j]*cas64[j][m] (transposed)
        const int u0 = (blk - NGEMM) * 16;
        #pragma unroll
        for (int q = 0; q < 2; q++) {
            int idx = tid + q * NTHR;
            sm.a.ws[idx >> 6][idx & 63] = w[u0 * 64 + idx];
        }
        if (tid < 64) {
            const float W1 = 2.0f * CUDART_PI_F / 64.0f;
            float s, c;
            __sincosf((float)tid * W1, &s, &c);
            sm.a.v64[tid] = c + s;
        }
        __syncthreads();
        #pragma unroll
        for (int q = 0; q < 8; q++) {
            int idx = tid + q * NTHR;
            int j = idx >> 6, m = idx & 63;
            sm.a.Cs[j][m] = sm.a.v64[(j * m) & 63];
        }
        __syncthreads();
        #pragma unroll
        for (int q = 0; q < 2; q++) {
            int idx = tid + q * NTHR;
            int ul = idx >> 6, m = idx & 63;
            float acc = 0.f;
            #pragma unroll
            for (int j = 0; j < 64; j++)
                acc = fmaf(sm.a.ws[ul][j], sm.a.Cs[j][m], acc);
            g_hq[m * 256 + u0 + ul] = acc;
        }
    }

    grid_bar();

    // ========== PHASE R (blocks 0-63) / C-table pregen (64-128) ==========
    if (blk < 64) {
        const int r = blk;
        if (tid < 64) {
            const float W1 = 2.0f * CUDART_PI_F / 64.0f;
            float s, c;
            __sincosf((float)tid * W1, &s, &c);
            sm.r.v64[tid] = c + s;
        }
        {
            const int pg = tid >> 6;          // 0..7, each sums 32 partials
            const int k  = tid & 63;
            const float* P = g_P + r * 64 + k + pg * 32 * 4096;
            float a0 = 0.f, a1 = 0.f, a2 = 0.f, a3 = 0.f;
            #pragma unroll
            for (int p = 0; p < 32; p += 4) {
                a0 += P[(p + 0) * 4096];
                a1 += P[(p + 1) * 4096];
                a2 += P[(p + 2) * 4096];
                a3 += P[(p + 3) * 4096];
            }
            sm.r.red[pg][k] = (a0 + a1) + (a2 + a3);
        }
        __syncthreads();
        if (tid < 64) {
            float s = 0.f;
            #pragma unroll
            for (int g = 0; g < 8; g++) s += sm.r.red[g][tid];
            sm.r.Ys[tid] = s;
        }
        __syncthreads();
        if (tid < 64) {
            const int m = tid;
            float acc = 0.f;
            #pragma unroll
            for (int k = 0; k < 64; k++)
                acc = fmaf(sm.r.Ys[k], sm.r.v64[(k * m) & 63], acc);
            sm.r.hps[m] = acc;
        }
        __syncthreads();
        if (tid < 64) {
            const int m = tid, mr = (64 - m) & 63;
            float a = sm.r.hps[m], b2 = sm.r.hps[mr];
            g_u[r * 64 + m] = a + b2;
            g_v[r * 64 + m] = a - b2;
        }
    } else if (blk < 129) {
        gen_ctab(sm.c.Cs, kbase, tid);   // idle blocks pregen C table
    }

    grid_bar();

    // ========== PHASE Z (blocks 0-3) / C-table pregen (4-63) ==========
    if (blk < 4) {
        const int b = blk;
        if (tid < 64) {
            const float W1 = 2.0f * CUDART_PI_F / 64.0f;
            float s, c;
            __sincosf((float)tid * W1, &s, &c);
            sm.z.v64[tid] = c + s;
        }
        #pragma unroll
        for (int q = 0; q < 2; q++) {
            int idx = tid + q * NTHR;
            int i = idx >> 6, m = idx & 63;
            sm.z.u16[i][m] = g_u[b * 1024 + idx];
            sm.z.v16[i][m] = g_v[b * 1024 + idx];
        }
        __syncthreads();
        #pragma unroll
        for (int q = 0; q < 2; q++) {
            int idx = tid + q * NTHR;
            int m = idx >> 4, o = idx & 15;
            int mr = (64 - m) & 63;
            const float* hq1 = g_hq + m  * 256 + o;
            const float* hq2 = g_hq + mr * 256 + o;
            float acc = 0.f;
            #pragma unroll
            for (int i = 0; i < 16; i++) {
                acc = fmaf(sm.z.u16[i][m], hq1[i * 16], acc);
                acc = fmaf(sm.z.v16[i][m], hq2[i * 16], acc);
            }
            sm.z.hzs[o][m] = 0.5f * acc;
        }
        __syncthreads();
        #pragma unroll
        for (int q = 0; q < 2; q++) {
            int idx = tid + q * NTHR;
            int o = idx >> 6, mp = idx & 63;
            float acc = 0.f;
            #pragma unroll
            for (int m = 0; m < 64; m++)
                acc = fmaf(sm.z.hzs[o][m], sm.z.v64[(m * mp) & 63], acc);
            g_zT[mp * 64 + b * 16 + o] = acc * (1.0f / 4096.0f);
        }
    } else if (blk < 64) {
        gen_ctab(sm.c.Cs, kbase, tid);   // blocks 4-63 pregen here
    }

    grid_bar();

    // ================= PHASE C: final DHT (129 blocks) =================
    if (blk < 129) {
        if (blk < 4)
            gen_ctab(sm.c.Cs, kbase, tid);   // Z-workers regen
        // load zT (hot in L2)
        #pragma unroll
        for (int q = 0; q < 2; q++) {
            int i4 = tid + q * NTHR;
            float4 v = *reinterpret_cast<const float4*>(g_zT + i4 * 4);
            int f = i4 * 4;
            *reinterpret_cast<float4*>(&sm.c.zs[f >> 6][f & 63]) = v;
        }
        __syncthreads();

        const int ktq = tid & 31;
        const int rq  = tid >> 5;
        const int r0  = rq * 4;
        const int k   = kbase + ktq;
        float a0 = 0.f, a1 = 0.f, a2 = 0.f, a3 = 0.f;
        #pragma unroll
        for (int mm = 0; mm < 64; mm++) {
            float4 zv = *reinterpret_cast<const float4*>(&sm.c.zs[mm][r0]);
            float cv = sm.c.Cs[mm][ktq];
            a0 = fmaf(zv.x, cv, a0);
            a1 = fmaf(zv.y, cv, a1);
            a2 = fmaf(zv.z, cv, a2);
            a3 = fmaf(zv.w, cv, a3);
        }
        const float SCL = 1.0f / 262208.0f;
        if (k < N2) {
            out[(r0 + 0) * N2 + k] = a0 * SCL;
            out[(r0 + 1) * N2 + k] = a1 * SCL;
            out[(r0 + 2) * N2 + k] = a2 * SCL;
            out[(r0 + 3) * N2 + k] = a3 * SCL;
        }
    }
}

// ============================================================
extern "C" void kernel_launch(void* const* d_in, const int* in_sizes, int n_in,
                              void* d_out, int out_size)
{
    const float* x = (const float*)d_in[0];   // [4,16,8192]
    const float* w = (const float*)d_in[1];   // [16,16,64]
    float* out = (float*)d_out;               // [4,16,4097]

    k_fused<<<NBLK, NTHR>>>(x, w, out);
}